// round 3
// baseline (speedup 1.0000x reference)
#include <cuda_runtime.h>
#include <math.h>

#define BATCH 1024
#define SEQT 128
#define HIDDEN 512
#define NLAYER 4
#define PRED 10
#define INDIM 6
#define OUTDIM 6
#define NT (BATCH*SEQT)            // 131072
#define ENC_ELEMS (NT*HIDDEN)      // 67108864

// ---------------- scratch (device globals; no allocation allowed) ----------------
__device__ float g_bufA[NT*HIDDEN];            // 256 MB (single big scratch)
__device__ float g_hA[BATCH*HIDDEN];
__device__ float g_hB[BATCH*HIDDEN];
__device__ float g_hd[2*NLAYER*BATCH*HIDDEN];  // decoder hidden ping-pong
__device__ float g_x0[BATCH*HIDDEN];
__device__ float g_decout[BATCH*PRED*HIDDEN];  // 20 MB

// ---------------- layer-0 projection: [NT,6] @ [512,6]^T + bih ----------------
__global__ void __launch_bounds__(512) proj0_kernel(const float* __restrict__ x,
    const float* __restrict__ W, const float* __restrict__ bias, float* __restrict__ out)
{
    __shared__ float Ws[HIDDEN*INDIM];
    __shared__ float bs[HIDDEN];
    __shared__ float xs[32][INDIM];
    int tid = threadIdx.x;
    for (int i = tid; i < HIDDEN*INDIM; i += 512) Ws[i] = W[i];
    if (tid < HIDDEN) bs[tid] = bias[tid];
    int r0 = blockIdx.x * 32;
    if (tid < 32*INDIM) xs[tid/INDIM][tid%INDIM] = x[(size_t)(r0 + tid/INDIM)*INDIM + tid%INDIM];
    __syncthreads();
    int h = tid;
    #pragma unroll 4
    for (int r = 0; r < 32; r++) {
        float acc = bs[h];
        #pragma unroll
        for (int d = 0; d < INDIM; d++) acc += xs[r][d] * Ws[h*INDIM + d];
        out[(size_t)(r0 + r)*HIDDEN + h] = acc;
    }
}

// ---------------- projection GEMM: C[m,n] = sum_k A[m,k]*W[n,k] + bias[n] ----------------
// M = NT, N = 512, K = 512. Tile 128x128x16, 256 threads, 8x8 per thread.
__global__ void __launch_bounds__(256) proj_gemm(const float* __restrict__ A,
    const float* __restrict__ W, const float* __restrict__ bias, float* __restrict__ C)
{
    __shared__ float As[16][132];
    __shared__ float Ws[16][132];
    int tid = threadIdx.x;
    int bm = blockIdx.x * 128;
    int bn = blockIdx.y * 128;
    float acc[8][8];
    #pragma unroll
    for (int i = 0; i < 8; i++)
        #pragma unroll
        for (int j = 0; j < 8; j++) acc[i][j] = 0.f;
    int tx = tid & 15, ty = tid >> 4;

    for (int k0 = 0; k0 < HIDDEN; k0 += 16) {
        #pragma unroll
        for (int i = 0; i < 2; i++) {
            int f4 = tid + i*256;
            int r = f4 >> 2, kq = (f4 & 3) << 2;
            float4 av = *(const float4*)(A + (size_t)(bm + r)*HIDDEN + k0 + kq);
            As[kq+0][r]=av.x; As[kq+1][r]=av.y; As[kq+2][r]=av.z; As[kq+3][r]=av.w;
            float4 wv = *(const float4*)(W + (size_t)(bn + r)*HIDDEN + k0 + kq);
            Ws[kq+0][r]=wv.x; Ws[kq+1][r]=wv.y; Ws[kq+2][r]=wv.z; Ws[kq+3][r]=wv.w;
        }
        __syncthreads();
        #pragma unroll
        for (int kk = 0; kk < 16; kk++) {
            float a[8], b[8];
            *(float4*)(a)   = *(const float4*)&As[kk][ty*8];
            *(float4*)(a+4) = *(const float4*)&As[kk][ty*8+4];
            *(float4*)(b)   = *(const float4*)&Ws[kk][tx*8];
            *(float4*)(b+4) = *(const float4*)&Ws[kk][tx*8+4];
            #pragma unroll
            for (int i = 0; i < 8; i++)
                #pragma unroll
                for (int j = 0; j < 8; j++) acc[i][j] += a[i]*b[j];
        }
        __syncthreads();
    }
    #pragma unroll
    for (int i = 0; i < 8; i++) {
        int m = bm + ty*8 + i;
        #pragma unroll
        for (int j = 0; j < 8; j++) {
            int n = bn + tx*8 + j;
            C[(size_t)m*HIDDEN + n] = acc[i][j] + bias[n];
        }
    }
}

// ---------------- recurrent step GEMM ----------------
// v = tanh( A1@W1^T + b1 [+ A2@W2^T + b2] [+ addend] ); out1 = v; out2 (opt) = v
// M = 1024, N = 512, K = 512 (x2 if DUAL). Tile 64x64x16, 256 threads, 4x4 per thread.
template<bool DUAL>
__global__ void __launch_bounds__(256) step_gemm(
    const float* __restrict__ A1, const float* __restrict__ W1, const float* __restrict__ b1,
    const float* __restrict__ A2, const float* __restrict__ W2, const float* __restrict__ b2,
    const float* __restrict__ addend, int addStride,
    float* __restrict__ out1, int out1Stride,
    float* __restrict__ out2, int out2Stride)
{
    __shared__ float As[16][68];
    __shared__ float Ws[16][68];
    int tid = threadIdx.x;
    int bm = blockIdx.x * 64;
    int bn = blockIdx.y * 64;
    float acc[4][4];
    #pragma unroll
    for (int i = 0; i < 4; i++)
        #pragma unroll
        for (int j = 0; j < 4; j++) acc[i][j] = 0.f;
    int tx = tid & 15, ty = tid >> 4;
    int r = tid >> 2, kq = (tid & 3) << 2;

    const float* Ap = A1;
    const float* Wp = W1;
    int npass = DUAL ? 2 : 1;
    for (int pass = 0; pass < npass; pass++) {
        for (int k0 = 0; k0 < HIDDEN; k0 += 16) {
            float4 av = *(const float4*)(Ap + (size_t)(bm + r)*HIDDEN + k0 + kq);
            As[kq+0][r]=av.x; As[kq+1][r]=av.y; As[kq+2][r]=av.z; As[kq+3][r]=av.w;
            float4 wv = *(const float4*)(Wp + (size_t)(bn + r)*HIDDEN + k0 + kq);
            Ws[kq+0][r]=wv.x; Ws[kq+1][r]=wv.y; Ws[kq+2][r]=wv.z; Ws[kq+3][r]=wv.w;
            __syncthreads();
            #pragma unroll
            for (int kk = 0; kk < 16; kk++) {
                float a[4], b[4];
                *(float4*)a = *(const float4*)&As[kk][ty*4];
                *(float4*)b = *(const float4*)&Ws[kk][tx*4];
                #pragma unroll
                for (int i = 0; i < 4; i++)
                    #pragma unroll
                    for (int j = 0; j < 4; j++) acc[i][j] += a[i]*b[j];
            }
            __syncthreads();
        }
        Ap = A2; Wp = W2;
    }

    #pragma unroll
    for (int i = 0; i < 4; i++) {
        int m = bm + ty*4 + i;
        #pragma unroll
        for (int j = 0; j < 4; j++) {
            int n = bn + tx*4 + j;
            float v = acc[i][j] + b1[n];
            if (DUAL) v += b2[n];
            if (addend) v += addend[(size_t)m*addStride + n];
            v = tanhf(v);
            out1[(size_t)m*out1Stride + n] = v;
            if (out2) out2[(size_t)m*out2Stride + n] = v;
        }
    }
}

// ---------------- strided row copy: dst[b*512+h] = src[b*stride + h] ----------------
__global__ void copy_rows(const float* __restrict__ src, int srcStride, float* __restrict__ dst)
{
    dst[(size_t)blockIdx.x*HIDDEN + threadIdx.x] =
        src[(size_t)blockIdx.x*srcStride + threadIdx.x];
}

// ---------------- final FC: [B*PRED,512] @ [6,512]^T + b ----------------
__global__ void __launch_bounds__(256) fc_kernel(const float* __restrict__ X,
    const float* __restrict__ W, const float* __restrict__ bias, float* __restrict__ out)
{
    __shared__ float Ws[OUTDIM][HIDDEN];
    int tid = threadIdx.x;
    for (int i = tid; i < OUTDIM*HIDDEN; i += 256) Ws[i/HIDDEN][i%HIDDEN] = W[i];
    __syncthreads();
    int warp = tid >> 5, lane = tid & 31;
    int row = blockIdx.x*8 + warp;
    float s[OUTDIM];
    #pragma unroll
    for (int o = 0; o < OUTDIM; o++) s[o] = 0.f;
    for (int k = lane; k < HIDDEN; k += 32) {
        float xv = X[(size_t)row*HIDDEN + k];
        #pragma unroll
        for (int o = 0; o < OUTDIM; o++) s[o] += xv * Ws[o][k];
    }
    #pragma unroll
    for (int o = 0; o < OUTDIM; o++) {
        #pragma unroll
        for (int off = 16; off; off >>= 1) s[o] += __shfl_down_sync(0xffffffffu, s[o], off);
    }
    if (lane == 0) {
        #pragma unroll
        for (int o = 0; o < OUTDIM; o++) out[(size_t)row*OUTDIM + o] = s[o] + bias[o];
    }
}

extern "C" void kernel_launch(void* const* d_in, const int* in_sizes, int n_in,
                              void* d_out, int out_size)
{
    (void)in_sizes; (void)n_in; (void)out_size;
    const float* x     = (const float*)d_in[0];
    const float* eWih0 = (const float*)d_in[1];
    const float* eWih  = (const float*)d_in[2];
    const float* eWhh  = (const float*)d_in[3];
    const float* ebih  = (const float*)d_in[4];
    const float* ebhh  = (const float*)d_in[5];
    const float* dWih  = (const float*)d_in[6];
    const float* dWhh  = (const float*)d_in[7];
    const float* dbih  = (const float*)d_in[8];
    const float* dbhh  = (const float*)d_in[9];
    const float* fcW   = (const float*)d_in[10];
    const float* fcb   = (const float*)d_in[11];

    float* out = (float*)d_out;
    float* enc_out = out;                             // [B, T, H] (also used as scratch)
    float* dec_final = out + (size_t)ENC_ELEMS;       // [B, PRED, OUT]

    float *bufA, *hA, *hB, *hd, *x0, *dout;
    cudaGetSymbolAddress((void**)&bufA, g_bufA);
    cudaGetSymbolAddress((void**)&hA,   g_hA);
    cudaGetSymbolAddress((void**)&hB,   g_hB);
    cudaGetSymbolAddress((void**)&hd,   g_hd);
    cudaGetSymbolAddress((void**)&x0,   g_x0);
    cudaGetSymbolAddress((void**)&dout, g_decout);

    const int addStride = SEQT*HIDDEN;   // 65536
    dim3 sg(BATCH/64, HIDDEN/64);        // step grid: 16 x 8
    dim3 pgrid(NT/128, HIDDEN/128);

    // ================= encoder =================
    // Buffer plan (seq output of layer l written in-place over its xW buffer):
    //   l0: xW -> bufA     (recurrence in-place; seq0 lives in bufA)
    //   l1: proj bufA -> enc_out  (seq1 in enc_out)
    //   l2: proj enc_out -> bufA  (seq2 in bufA)
    //   l3: proj bufA -> enc_out  (seq3 = final enc_outputs in enc_out)
    for (int l = 0; l < NLAYER; l++) {
        float* xw;
        if (l == 0) {
            xw = bufA;
            proj0_kernel<<<NT/32, 512>>>(x, eWih0, ebih, xw);
        } else {
            const float* pin = (l == 2) ? enc_out : bufA;
            xw              = (l == 2) ? bufA : enc_out;
            proj_gemm<<<pgrid, 256>>>(pin, eWih + (size_t)(l-1)*HIDDEN*HIDDEN,
                                      ebih + l*HIDDEN, xw);
        }
        float* seqOut = xw;   // in-place: h_t overwrites xW_t after it's consumed

        cudaMemsetAsync(hA, 0, (size_t)BATCH*HIDDEN*sizeof(float), 0);
        for (int t = 0; t < SEQT; t++) {
            const float* hin = (t & 1) ? hB : hA;
            float* hout      = (t & 1) ? hA : hB;
            step_gemm<false><<<sg, 256>>>(
                hin, eWhh + (size_t)l*HIDDEN*HIDDEN, ebhh + l*HIDDEN,
                nullptr, nullptr, nullptr,
                xw + (size_t)t*HIDDEN, addStride,
                seqOut + (size_t)t*HIDDEN, addStride,
                hout, HIDDEN);
        }
        // final hidden h_enc[l] = seqOut[:, T-1, :]
        copy_rows<<<BATCH, HIDDEN>>>(seqOut + (size_t)(SEQT-1)*HIDDEN, addStride,
                                     hd + (size_t)l*BATCH*HIDDEN);
    }

    // ================= decoder =================
    copy_rows<<<BATCH, HIDDEN>>>(enc_out + (size_t)(SEQT-1)*HIDDEN, addStride, x0);

    int cur = 0;
    const float* xin = x0;
    for (int p = 0; p < PRED; p++) {
        int nxt = cur ^ 1;
        for (int l = 0; l < NLAYER; l++) {
            float* hnew = hd + ((size_t)nxt*NLAYER + l)*BATCH*HIDDEN;
            float* o2 = (l == NLAYER-1) ? (dout + (size_t)p*HIDDEN) : nullptr;
            step_gemm<true><<<sg, 256>>>(
                xin, dWih + (size_t)l*HIDDEN*HIDDEN, dbih + l*HIDDEN,
                hd + ((size_t)cur*NLAYER + l)*BATCH*HIDDEN,
                dWhh + (size_t)l*HIDDEN*HIDDEN, dbhh + l*HIDDEN,
                nullptr, 0,
                hnew, HIDDEN,
                o2, PRED*HIDDEN);
            xin = hnew;
        }
        cur = nxt;
    }

    // ================= final FC =================
    fc_kernel<<<BATCH*PRED/8, 256>>>(dout, fcW, fcb, dec_final);
}

// round 4
// speedup vs baseline: 1.0026x; 1.0026x over previous
#include <cuda_runtime.h>
#include <math.h>

#define BATCH 1024
#define SEQT 128
#define HIDDEN 512
#define NLAYER 4
#define PRED 10
#define INDIM 6
#define OUTDIM 6
#define NT (BATCH*SEQT)            // 131072
#define ENC_ELEMS (NT*HIDDEN)      // 67108864

// ---------------- scratch (device globals; no allocation allowed) ----------------
__device__ float g_bufA[NT*HIDDEN];            // 256 MB (single big scratch)
__device__ float g_hA[BATCH*HIDDEN];
__device__ float g_hB[BATCH*HIDDEN];
__device__ float g_hd[2*NLAYER*BATCH*HIDDEN];  // decoder hidden ping-pong
__device__ float g_x0[BATCH*HIDDEN];
__device__ float g_decout[BATCH*PRED*HIDDEN];  // 20 MB

// ---------------- layer-0 projection: [NT,6] @ [512,6]^T + bih ----------------
__global__ void __launch_bounds__(512) proj0_kernel(const float* __restrict__ x,
    const float* __restrict__ W, const float* __restrict__ bias, float* __restrict__ out)
{
    __shared__ float Ws[HIDDEN*INDIM];
    __shared__ float bs[HIDDEN];
    __shared__ float xs[32][INDIM];
    int tid = threadIdx.x;
    for (int i = tid; i < HIDDEN*INDIM; i += 512) Ws[i] = W[i];
    if (tid < HIDDEN) bs[tid] = bias[tid];
    int r0 = blockIdx.x * 32;
    if (tid < 32*INDIM) xs[tid/INDIM][tid%INDIM] = x[(size_t)(r0 + tid/INDIM)*INDIM + tid%INDIM];
    __syncthreads();
    int h = tid;
    #pragma unroll 4
    for (int r = 0; r < 32; r++) {
        float acc = bs[h];
        #pragma unroll
        for (int d = 0; d < INDIM; d++) acc += xs[r][d] * Ws[h*INDIM + d];
        out[(size_t)(r0 + r)*HIDDEN + h] = acc;
    }
}

// ---------------- projection GEMM: C[m,n] = sum_k A[m,k]*W[n,k] + bias[n] ----------------
// M = NT, N = 512, K = 512. Tile 128x128x16, 256 threads, 8x8 per thread.
__global__ void __launch_bounds__(256) proj_gemm(const float* __restrict__ A,
    const float* __restrict__ W, const float* __restrict__ bias, float* __restrict__ C)
{
    __shared__ float As[16][132];
    __shared__ float Ws[16][132];
    int tid = threadIdx.x;
    int bm = blockIdx.x * 128;
    int bn = blockIdx.y * 128;
    float acc[8][8];
    #pragma unroll
    for (int i = 0; i < 8; i++)
        #pragma unroll
        for (int j = 0; j < 8; j++) acc[i][j] = 0.f;
    int tx = tid & 15, ty = tid >> 4;

    for (int k0 = 0; k0 < HIDDEN; k0 += 16) {
        #pragma unroll
        for (int i = 0; i < 2; i++) {
            int f4 = tid + i*256;
            int r = f4 >> 2, kq = (f4 & 3) << 2;
            float4 av = *(const float4*)(A + (size_t)(bm + r)*HIDDEN + k0 + kq);
            As[kq+0][r]=av.x; As[kq+1][r]=av.y; As[kq+2][r]=av.z; As[kq+3][r]=av.w;
            float4 wv = *(const float4*)(W + (size_t)(bn + r)*HIDDEN + k0 + kq);
            Ws[kq+0][r]=wv.x; Ws[kq+1][r]=wv.y; Ws[kq+2][r]=wv.z; Ws[kq+3][r]=wv.w;
        }
        __syncthreads();
        #pragma unroll
        for (int kk = 0; kk < 16; kk++) {
            float a[8], b[8];
            *(float4*)(a)   = *(const float4*)&As[kk][ty*8];
            *(float4*)(a+4) = *(const float4*)&As[kk][ty*8+4];
            *(float4*)(b)   = *(const float4*)&Ws[kk][tx*8];
            *(float4*)(b+4) = *(const float4*)&Ws[kk][tx*8+4];
            #pragma unroll
            for (int i = 0; i < 8; i++)
                #pragma unroll
                for (int j = 0; j < 8; j++) acc[i][j] += a[i]*b[j];
        }
        __syncthreads();
    }
    #pragma unroll
    for (int i = 0; i < 8; i++) {
        int m = bm + ty*8 + i;
        #pragma unroll
        for (int j = 0; j < 8; j++) {
            int n = bn + tx*8 + j;
            C[(size_t)m*HIDDEN + n] = acc[i][j] + bias[n];
        }
    }
}

// ---------------- recurrent step GEMM ----------------
// v = tanh( A1@W1^T + b1 [+ A2@W2^T + b2] [+ addend] ); out1 = v; out2 (opt) = v
// M = 1024, N = 512, K = 512 (x2 if DUAL). Tile 64x64x16, 256 threads, 4x4 per thread.
template<bool DUAL>
__global__ void __launch_bounds__(256) step_gemm(
    const float* __restrict__ A1, const float* __restrict__ W1, const float* __restrict__ b1,
    const float* __restrict__ A2, const float* __restrict__ W2, const float* __restrict__ b2,
    const float* __restrict__ addend, int addStride,
    float* __restrict__ out1, int out1Stride,
    float* __restrict__ out2, int out2Stride)
{
    __shared__ float As[16][68];
    __shared__ float Ws[16][68];
    int tid = threadIdx.x;
    int bm = blockIdx.x * 64;
    int bn = blockIdx.y * 64;
    float acc[4][4];
    #pragma unroll
    for (int i = 0; i < 4; i++)
        #pragma unroll
        for (int j = 0; j < 4; j++) acc[i][j] = 0.f;
    int tx = tid & 15, ty = tid >> 4;
    int r = tid >> 2, kq = (tid & 3) << 2;

    const float* Ap = A1;
    const float* Wp = W1;
    int npass = DUAL ? 2 : 1;
    for (int pass = 0; pass < npass; pass++) {
        for (int k0 = 0; k0 < HIDDEN; k0 += 16) {
            float4 av = *(const float4*)(Ap + (size_t)(bm + r)*HIDDEN + k0 + kq);
            As[kq+0][r]=av.x; As[kq+1][r]=av.y; As[kq+2][r]=av.z; As[kq+3][r]=av.w;
            float4 wv = *(const float4*)(Wp + (size_t)(bn + r)*HIDDEN + k0 + kq);
            Ws[kq+0][r]=wv.x; Ws[kq+1][r]=wv.y; Ws[kq+2][r]=wv.z; Ws[kq+3][r]=wv.w;
            __syncthreads();
            #pragma unroll
            for (int kk = 0; kk < 16; kk++) {
                float a[4], b[4];
                *(float4*)a = *(const float4*)&As[kk][ty*4];
                *(float4*)b = *(const float4*)&Ws[kk][tx*4];
                #pragma unroll
                for (int i = 0; i < 4; i++)
                    #pragma unroll
                    for (int j = 0; j < 4; j++) acc[i][j] += a[i]*b[j];
            }
            __syncthreads();
        }
        Ap = A2; Wp = W2;
    }

    #pragma unroll
    for (int i = 0; i < 4; i++) {
        int m = bm + ty*4 + i;
        #pragma unroll
        for (int j = 0; j < 4; j++) {
            int n = bn + tx*4 + j;
            float v = acc[i][j] + b1[n];
            if (DUAL) v += b2[n];
            if (addend) v += addend[(size_t)m*addStride + n];
            v = tanhf(v);
            out1[(size_t)m*out1Stride + n] = v;
            if (out2) out2[(size_t)m*out2Stride + n] = v;
        }
    }
}

// ---------------- strided row copy: dst[b*512+h] = src[b*stride + h] ----------------
__global__ void copy_rows(const float* __restrict__ src, int srcStride, float* __restrict__ dst)
{
    dst[(size_t)blockIdx.x*HIDDEN + threadIdx.x] =
        src[(size_t)blockIdx.x*srcStride + threadIdx.x];
}

// ---------------- final FC: [B*PRED,512] @ [6,512]^T + b ----------------
__global__ void __launch_bounds__(256) fc_kernel(const float* __restrict__ X,
    const float* __restrict__ W, const float* __restrict__ bias, float* __restrict__ out)
{
    __shared__ float Ws[OUTDIM][HIDDEN];
    int tid = threadIdx.x;
    for (int i = tid; i < OUTDIM*HIDDEN; i += 256) Ws[i/HIDDEN][i%HIDDEN] = W[i];
    __syncthreads();
    int warp = tid >> 5, lane = tid & 31;
    int row = blockIdx.x*8 + warp;
    float s[OUTDIM];
    #pragma unroll
    for (int o = 0; o < OUTDIM; o++) s[o] = 0.f;
    for (int k = lane; k < HIDDEN; k += 32) {
        float xv = X[(size_t)row*HIDDEN + k];
        #pragma unroll
        for (int o = 0; o < OUTDIM; o++) s[o] += xv * Ws[o][k];
    }
    #pragma unroll
    for (int o = 0; o < OUTDIM; o++) {
        #pragma unroll
        for (int off = 16; off; off >>= 1) s[o] += __shfl_down_sync(0xffffffffu, s[o], off);
    }
    if (lane == 0) {
        #pragma unroll
        for (int o = 0; o < OUTDIM; o++) out[(size_t)row*OUTDIM + o] = s[o] + bias[o];
    }
}

extern "C" void kernel_launch(void* const* d_in, const int* in_sizes, int n_in,
                              void* d_out, int out_size)
{
    (void)in_sizes; (void)n_in; (void)out_size;
    const float* x     = (const float*)d_in[0];
    const float* eWih0 = (const float*)d_in[1];
    const float* eWih  = (const float*)d_in[2];
    const float* eWhh  = (const float*)d_in[3];
    const float* ebih  = (const float*)d_in[4];
    const float* ebhh  = (const float*)d_in[5];
    const float* dWih  = (const float*)d_in[6];
    const float* dWhh  = (const float*)d_in[7];
    const float* dbih  = (const float*)d_in[8];
    const float* dbhh  = (const float*)d_in[9];
    const float* fcW   = (const float*)d_in[10];
    const float* fcb   = (const float*)d_in[11];

    float* out = (float*)d_out;
    float* enc_out = out;                             // [B, T, H] (also used as scratch)
    float* dec_final = out + (size_t)ENC_ELEMS;       // [B, PRED, OUT]

    float *bufA, *hA, *hB, *hd, *x0, *dout;
    cudaGetSymbolAddress((void**)&bufA, g_bufA);
    cudaGetSymbolAddress((void**)&hA,   g_hA);
    cudaGetSymbolAddress((void**)&hB,   g_hB);
    cudaGetSymbolAddress((void**)&hd,   g_hd);
    cudaGetSymbolAddress((void**)&x0,   g_x0);
    cudaGetSymbolAddress((void**)&dout, g_decout);

    const int addStride = SEQT*HIDDEN;   // 65536
    dim3 sg(BATCH/64, HIDDEN/64);        // step grid: 16 x 8
    dim3 pgrid(NT/128, HIDDEN/128);

    // ================= encoder =================
    // Buffer plan (seq output of layer l written in-place over its xW buffer):
    //   l0: xW -> bufA     (recurrence in-place; seq0 lives in bufA)
    //   l1: proj bufA -> enc_out  (seq1 in enc_out)
    //   l2: proj enc_out -> bufA  (seq2 in bufA)
    //   l3: proj bufA -> enc_out  (seq3 = final enc_outputs in enc_out)
    for (int l = 0; l < NLAYER; l++) {
        float* xw;
        if (l == 0) {
            xw = bufA;
            proj0_kernel<<<NT/32, 512>>>(x, eWih0, ebih, xw);
        } else {
            const float* pin = (l == 2) ? enc_out : bufA;
            xw              = (l == 2) ? bufA : enc_out;
            proj_gemm<<<pgrid, 256>>>(pin, eWih + (size_t)(l-1)*HIDDEN*HIDDEN,
                                      ebih + l*HIDDEN, xw);
        }
        float* seqOut = xw;   // in-place: h_t overwrites xW_t after it's consumed

        cudaMemsetAsync(hA, 0, (size_t)BATCH*HIDDEN*sizeof(float), 0);
        for (int t = 0; t < SEQT; t++) {
            const float* hin = (t & 1) ? hB : hA;
            float* hout      = (t & 1) ? hA : hB;
            step_gemm<false><<<sg, 256>>>(
                hin, eWhh + (size_t)l*HIDDEN*HIDDEN, ebhh + l*HIDDEN,
                nullptr, nullptr, nullptr,
                xw + (size_t)t*HIDDEN, addStride,
                seqOut + (size_t)t*HIDDEN, addStride,
                hout, HIDDEN);
        }
        // final hidden h_enc[l] = seqOut[:, T-1, :]
        copy_rows<<<BATCH, HIDDEN>>>(seqOut + (size_t)(SEQT-1)*HIDDEN, addStride,
                                     hd + (size_t)l*BATCH*HIDDEN);
    }

    // ================= decoder =================
    copy_rows<<<BATCH, HIDDEN>>>(enc_out + (size_t)(SEQT-1)*HIDDEN, addStride, x0);

    int cur = 0;
    const float* xin = x0;
    for (int p = 0; p < PRED; p++) {
        int nxt = cur ^ 1;
        for (int l = 0; l < NLAYER; l++) {
            float* hnew = hd + ((size_t)nxt*NLAYER + l)*BATCH*HIDDEN;
            float* o2 = (l == NLAYER-1) ? (dout + (size_t)p*HIDDEN) : nullptr;
            step_gemm<true><<<sg, 256>>>(
                xin, dWih + (size_t)l*HIDDEN*HIDDEN, dbih + l*HIDDEN,
                hd + ((size_t)cur*NLAYER + l)*BATCH*HIDDEN,
                dWhh + (size_t)l*HIDDEN*HIDDEN, dbhh + l*HIDDEN,
                nullptr, 0,
                hnew, HIDDEN,
                o2, PRED*HIDDEN);
            xin = hnew;
        }
        cur = nxt;
    }

    // ================= final FC =================
    fc_kernel<<<BATCH*PRED/8, 256>>>(dout, fcW, fcb, dec_final);
}

// round 5
// speedup vs baseline: 1.4351x; 1.4314x over previous
#include <cuda_runtime.h>
#include <math.h>

#define BATCH 1024
#define SEQT 128
#define HIDDEN 512
#define HH (HIDDEN*HIDDEN)
#define BH (BATCH*HIDDEN)
#define NLAYER 4
#define PRED 10
#define INDIM 6
#define OUTDIM 6
#define NT (BATCH*SEQT)
#define ENC_ELEMS (NT*HIDDEN)

typedef unsigned long long u64;

// ---------------- scratch (device globals; no allocation allowed) ----------------
__device__ float g_h[NLAYER*2*BH];            // encoder hidden ping-pong [layer][parity][B*H]
__device__ float g_hd[2*NLAYER*BH];           // decoder hidden ping-pong [parity][layer][B*H]
__device__ float g_part[4*BH];                // split-K partials
__device__ float g_decout[BATCH*PRED*HIDDEN]; // decoder outputs for FC

// ---------------- f32x2 helpers ----------------
__device__ __forceinline__ u64 ffma2(u64 a, u64 b, u64 c){
    u64 d; asm("fma.rn.f32x2 %0, %1, %2, %3;" : "=l"(d) : "l"(a), "l"(b), "l"(c)); return d;
}
__device__ __forceinline__ u64 dup2(float x){
    u64 d; asm("mov.b64 %0, {%1, %1};" : "=l"(d) : "f"(x)); return d;
}
__device__ __forceinline__ u64 pack2(float lo, float hi){
    u64 d; asm("mov.b64 %0, {%1, %2};" : "=l"(d) : "f"(lo), "f"(hi)); return d;
}
__device__ __forceinline__ float2 unpk(u64 v){
    float2 r; asm("mov.b64 {%0, %1}, %2;" : "=f"(r.x), "=f"(r.y) : "l"(v)); return r;
}

// ---------------- MUFU-free tanh ----------------
__device__ __forceinline__ float fast_tanh(float x){
    float cx = fminf(fmaxf(x, -9.5f), 9.5f);
    float z  = cx * 2.8853900818f;               // 2x * log2(e)
    float y  = z + 12582912.0f;                  // round to nearest int
    int   n  = __float_as_int(y) - 0x4B400000;
    float f  = z - (y - 12582912.0f);            // [-0.5, 0.5]
    float t = 1.5252733e-05f;
    t = fmaf(t, f, 1.5403530e-04f);
    t = fmaf(t, f, 1.3333558e-03f);
    t = fmaf(t, f, 9.6181291e-03f);
    t = fmaf(t, f, 5.5504109e-02f);
    t = fmaf(t, f, 2.4022651e-01f);
    t = fmaf(t, f, 6.9314718e-01f);
    t = t * f;                                   // 2^f - 1
    float s   = __int_as_float((n + 127) << 23);
    float em1 = fmaf(s, t, s - 1.0f);            // e^{2x} - 1
    float ep1 = em1 + 2.0f;
    float r = __int_as_float(0x7EF311C3 - __float_as_int(ep1));
    r = r * fmaf(-ep1, r, 2.0f);
    r = r * fmaf(-ep1, r, 2.0f);
    r = r * fmaf(-ep1, r, 2.0f);
    return em1 * r;
}

// ---------------- shared GEMM pass: acc += A[bm:bm+128, kb:ke] @ W[bn:bn+128, kb:ke]^T ----------------
// 256 threads, 8x8 per thread (f32x2 packed: 8x4 u64 accumulators).
#define STORE_SMEM() do { \
    As[kq+0][r0]=pa0.x; As[kq+1][r0]=pa0.y; As[kq+2][r0]=pa0.z; As[kq+3][r0]=pa0.w; \
    As[kq+0][r0+64]=pa1.x; As[kq+1][r0+64]=pa1.y; As[kq+2][r0+64]=pa1.z; As[kq+3][r0+64]=pa1.w; \
    Ws[kq+0][r0]=pw0.x; Ws[kq+1][r0]=pw0.y; Ws[kq+2][r0]=pw0.z; Ws[kq+3][r0]=pw0.w; \
    Ws[kq+0][r0+64]=pw1.x; Ws[kq+1][r0+64]=pw1.y; Ws[kq+2][r0+64]=pw1.z; Ws[kq+3][r0+64]=pw1.w; \
} while(0)

__device__ __forceinline__ void gemm_pass(
    const float* __restrict__ A, const float* __restrict__ W,
    int kb, int ke, int bm, int bn, int tid,
    float (*As)[132], float (*Ws)[132], u64 (*acc)[4])
{
    int tx = tid & 15, ty = tid >> 4;
    int r0 = tid >> 2, kq = (tid & 3) << 2;
    const float* Ab = A + (size_t)(bm + r0)*HIDDEN + kq;
    const float* Wb = W + (size_t)(bn + r0)*HIDDEN + kq;
    float4 pa0 = *(const float4*)(Ab + kb);
    float4 pa1 = *(const float4*)(Ab + 64*HIDDEN + kb);
    float4 pw0 = *(const float4*)(Wb + kb);
    float4 pw1 = *(const float4*)(Wb + 64*HIDDEN + kb);

    for (int k0 = kb; k0 < ke; k0 += 16) {
        __syncthreads();
        STORE_SMEM();
        __syncthreads();
        if (k0 + 16 < ke) {
            pa0 = *(const float4*)(Ab + k0 + 16);
            pa1 = *(const float4*)(Ab + 64*HIDDEN + k0 + 16);
            pw0 = *(const float4*)(Wb + k0 + 16);
            pw1 = *(const float4*)(Wb + 64*HIDDEN + k0 + 16);
        }
        #pragma unroll
        for (int kk = 0; kk < 16; kk++) {
            float av[8], bv[8];
            *(float4*)&av[0] = *(const float4*)&As[kk][ty*8];
            *(float4*)&av[4] = *(const float4*)&As[kk][ty*8 + 4];
            *(float4*)&bv[0] = *(const float4*)&Ws[kk][tx*8];
            *(float4*)&bv[4] = *(const float4*)&Ws[kk][tx*8 + 4];
            u64 b0 = pack2(bv[0], bv[1]), b1 = pack2(bv[2], bv[3]);
            u64 b2 = pack2(bv[4], bv[5]), b3 = pack2(bv[6], bv[7]);
            #pragma unroll
            for (int i = 0; i < 8; i++) {
                u64 ad = dup2(av[i]);
                acc[i][0] = ffma2(ad, b0, acc[i][0]);
                acc[i][1] = ffma2(ad, b1, acc[i][1]);
                acc[i][2] = ffma2(ad, b2, acc[i][2]);
                acc[i][3] = ffma2(ad, b3, acc[i][3]);
            }
        }
    }
}

// ---------------- layer-0 projection: [NT,6] @ [512,6]^T + bih0 -> enc_out region ----------------
__global__ void __launch_bounds__(512) proj0_kernel(const float* __restrict__ x,
    const float* __restrict__ W, const float* __restrict__ bias, float* __restrict__ out)
{
    __shared__ float Ws[HIDDEN*INDIM];
    __shared__ float bs[HIDDEN];
    __shared__ float xs[32][INDIM];
    int tid = threadIdx.x;
    for (int i = tid; i < HIDDEN*INDIM; i += 512) Ws[i] = W[i];
    if (tid < HIDDEN) bs[tid] = bias[tid];
    int r0 = blockIdx.x * 32;
    if (tid < 32*INDIM) xs[tid/INDIM][tid%INDIM] = x[(size_t)(r0 + tid/INDIM)*INDIM + tid%INDIM];
    __syncthreads();
    int h = tid;
    #pragma unroll 4
    for (int r = 0; r < 32; r++) {
        float acc = bs[h];
        #pragma unroll
        for (int d = 0; d < INDIM; d++) acc += xs[r][d] * Ws[h*INDIM + d];
        out[(size_t)(r0 + r)*HIDDEN + h] = acc;
    }
}

// ---------------- encoder wavefront superstep ----------------
// blockIdx.z = layer l; computes t = s - l.
// l==0: h0_t = tanh(xw0[:,t,:] + h0_{t-1} @ Whh0^T + bhh0)
// l>=1: hl_t = tanh(h_{l-1,t} @ Wih_l^T + h_{l,t-1} @ Whh_l^T + bih_l + bhh_l)
__global__ void __launch_bounds__(256, 1) wave_step(
    int s,
    const float* __restrict__ eWih, const float* __restrict__ eWhh,
    const float* __restrict__ ebih, const float* __restrict__ ebhh,
    float* __restrict__ hb, float* __restrict__ enc_out)
{
    int l = blockIdx.z;
    int t = s - l;
    if (t < 0 || t >= SEQT) return;
    int p_r = (s + 1) & 1, p_w = s & 1;

    __shared__ __align__(16) float As[16][132];
    __shared__ __align__(16) float Ws[16][132];
    int tid = threadIdx.x;
    int bm = blockIdx.x * 128, bn = blockIdx.y * 128;
    int tx = tid & 15, ty = tid >> 4;

    u64 acc[8][4];
    #pragma unroll
    for (int i = 0; i < 8; i++)
        #pragma unroll
        for (int j = 0; j < 4; j++) acc[i][j] = 0ull;

    if (l == 0) {
        gemm_pass(hb + (size_t)p_r*BH, eWhh, 0, HIDDEN, bm, bn, tid, As, Ws, acc);
    } else {
        gemm_pass(hb + ((size_t)(l-1)*2 + p_r)*BH, eWih + (size_t)(l-1)*HH, 0, HIDDEN, bm, bn, tid, As, Ws, acc);
        gemm_pass(hb + ((size_t)l*2 + p_r)*BH,     eWhh + (size_t)l*HH,     0, HIDDEN, bm, bn, tid, As, Ws, acc);
    }

    int n0 = bn + tx*8;
    float bias8[8];
    #pragma unroll
    for (int j = 0; j < 8; j++) {
        bias8[j] = ebhh[l*HIDDEN + n0 + j];
        if (l > 0) bias8[j] += ebih[l*HIDDEN + n0 + j];
    }
    float* hout = hb + ((size_t)l*2 + p_w)*BH;

    #pragma unroll
    for (int i = 0; i < 8; i++) {
        int m = bm + ty*8 + i;
        float o[8];
        #pragma unroll
        for (int j = 0; j < 4; j++) { float2 v = unpk(acc[i][j]); o[2*j] = v.x; o[2*j+1] = v.y; }
        if (l == 0) {
            const float* xr = enc_out + ((size_t)m*SEQT + t)*HIDDEN + n0;
            #pragma unroll
            for (int j = 0; j < 8; j++) o[j] += xr[j];
        }
        #pragma unroll
        for (int j = 0; j < 8; j++) o[j] = fast_tanh(o[j] + bias8[j]);
        float4* dst = (float4*)(hout + (size_t)m*HIDDEN + n0);
        dst[0] = make_float4(o[0], o[1], o[2], o[3]);
        dst[1] = make_float4(o[4], o[5], o[6], o[7]);
        if (l == 3) {
            float4* d2 = (float4*)(enc_out + ((size_t)m*SEQT + t)*HIDDEN + n0);
            d2[0] = make_float4(o[0], o[1], o[2], o[3]);
            d2[1] = make_float4(o[4], o[5], o[6], o[7]);
        }
    }
}

// ---------------- decoder split-K partial: part[z] = chunk of x@Wih^T + h@Whh^T ----------------
__global__ void __launch_bounds__(256, 1) dec_partial(
    const float* __restrict__ xin, const float* __restrict__ Wih,
    const float* __restrict__ hin, const float* __restrict__ Whh,
    float* __restrict__ part)
{
    __shared__ __align__(16) float As[16][132];
    __shared__ __align__(16) float Ws[16][132];
    int tid = threadIdx.x;
    int bm = blockIdx.x * 128, bn = blockIdx.y * 128;
    int z = blockIdx.z;
    int tx = tid & 15, ty = tid >> 4;

    u64 acc[8][4];
    #pragma unroll
    for (int i = 0; i < 8; i++)
        #pragma unroll
        for (int j = 0; j < 4; j++) acc[i][j] = 0ull;

    const float* A = (z >> 1) ? hin : xin;
    const float* W = (z >> 1) ? Whh : Wih;
    int kb = (z & 1) * 256;
    gemm_pass(A, W, kb, kb + 256, bm, bn, tid, As, Ws, acc);

    float* dst = part + (size_t)z*BH;
    #pragma unroll
    for (int i = 0; i < 8; i++) {
        int m = bm + ty*8 + i;
        int n0 = bn + tx*8;
        float o[8];
        #pragma unroll
        for (int j = 0; j < 4; j++) { float2 v = unpk(acc[i][j]); o[2*j] = v.x; o[2*j+1] = v.y; }
        float4* d = (float4*)(dst + (size_t)m*HIDDEN + n0);
        d[0] = make_float4(o[0], o[1], o[2], o[3]);
        d[1] = make_float4(o[4], o[5], o[6], o[7]);
    }
}

// ---------------- decoder reduce: h = tanh(sum parts + bih + bhh) ----------------
__global__ void __launch_bounds__(256) dec_reduce(
    const float* __restrict__ part, const float* __restrict__ bih, const float* __restrict__ bhh,
    float* __restrict__ hout, float* __restrict__ dout)
{
    int e = blockIdx.x * blockDim.x + threadIdx.x;   // float4 index over BH/4
    int n = (e & 127) * 4;
    int m = e >> 7;
    size_t off = (size_t)e * 4;
    float4 s0 = *(const float4*)(part + off);
    float4 s1 = *(const float4*)(part + BH + off);
    float4 s2 = *(const float4*)(part + 2*(size_t)BH + off);
    float4 s3 = *(const float4*)(part + 3*(size_t)BH + off);
    float4 b1 = *(const float4*)(bih + n);
    float4 b2 = *(const float4*)(bhh + n);
    float4 v;
    v.x = fast_tanh(s0.x + s1.x + s2.x + s3.x + b1.x + b2.x);
    v.y = fast_tanh(s0.y + s1.y + s2.y + s3.y + b1.y + b2.y);
    v.z = fast_tanh(s0.z + s1.z + s2.z + s3.z + b1.z + b2.z);
    v.w = fast_tanh(s0.w + s1.w + s2.w + s3.w + b1.w + b2.w);
    *(float4*)(hout + off) = v;
    if (dout) *(float4*)(dout + (size_t)m*PRED*HIDDEN + n) = v;
}

// ---------------- final FC: [B*PRED,512] @ [6,512]^T + b ----------------
__global__ void __launch_bounds__(256) fc_kernel(const float* __restrict__ X,
    const float* __restrict__ W, const float* __restrict__ bias, float* __restrict__ out)
{
    __shared__ float Ws[OUTDIM][HIDDEN];
    int tid = threadIdx.x;
    for (int i = tid; i < OUTDIM*HIDDEN; i += 256) Ws[i/HIDDEN][i%HIDDEN] = W[i];
    __syncthreads();
    int warp = tid >> 5, lane = tid & 31;
    int row = blockIdx.x*8 + warp;
    float s[OUTDIM];
    #pragma unroll
    for (int o = 0; o < OUTDIM; o++) s[o] = 0.f;
    for (int k = lane; k < HIDDEN; k += 32) {
        float xv = X[(size_t)row*HIDDEN + k];
        #pragma unroll
        for (int o = 0; o < OUTDIM; o++) s[o] += xv * Ws[o][k];
    }
    #pragma unroll
    for (int o = 0; o < OUTDIM; o++) {
        #pragma unroll
        for (int off = 16; off; off >>= 1) s[o] += __shfl_down_sync(0xffffffffu, s[o], off);
    }
    if (lane == 0) {
        #pragma unroll
        for (int o = 0; o < OUTDIM; o++) out[(size_t)row*OUTDIM + o] = s[o] + bias[o];
    }
}

extern "C" void kernel_launch(void* const* d_in, const int* in_sizes, int n_in,
                              void* d_out, int out_size)
{
    (void)in_sizes; (void)n_in; (void)out_size;
    const float* x     = (const float*)d_in[0];
    const float* eWih0 = (const float*)d_in[1];
    const float* eWih  = (const float*)d_in[2];
    const float* eWhh  = (const float*)d_in[3];
    const float* ebih  = (const float*)d_in[4];
    const float* ebhh  = (const float*)d_in[5];
    const float* dWih  = (const float*)d_in[6];
    const float* dWhh  = (const float*)d_in[7];
    const float* dbih  = (const float*)d_in[8];
    const float* dbhh  = (const float*)d_in[9];
    const float* fcW   = (const float*)d_in[10];
    const float* fcb   = (const float*)d_in[11];

    float* out = (float*)d_out;
    float* enc_out = out;                             // [B, T, H] (staging for xw0, final enc output)
    float* dec_final = out + (size_t)ENC_ELEMS;       // [B, PRED, OUT]

    float *hb, *hd, *part, *dout;
    cudaGetSymbolAddress((void**)&hb,   g_h);
    cudaGetSymbolAddress((void**)&hd,   g_hd);
    cudaGetSymbolAddress((void**)&part, g_part);
    cudaGetSymbolAddress((void**)&dout, g_decout);

    // zero all encoder hidden ping-pong buffers (initial h_{-1} = 0 for every parity)
    cudaMemsetAsync(hb, 0, (size_t)NLAYER*2*BH*sizeof(float), 0);

    // layer-0 input projection (includes bih0) staged into enc_out
    proj0_kernel<<<NT/32, 512>>>(x, eWih0, ebih, enc_out);

    // encoder wavefront: supersteps s = 0 .. SEQT+NLAYER-2
    dim3 wg(BATCH/128, HIDDEN/128, NLAYER);   // 8 x 4 x 4
    for (int s = 0; s < SEQT + NLAYER - 1; s++)
        wave_step<<<wg, 256>>>(s, eWih, eWhh, ebih, ebhh, hb, enc_out);

    // decoder: 10 steps x 4 layers, split-K partial + reduce
    dim3 dg(BATCH/128, HIDDEN/128, 4);        // 8 x 4 x 4
    for (int p = 0; p < PRED; p++) {
        float* hdcur  = hd + (size_t)(p & 1)*NLAYER*BH;
        float* hdprev = hd + (size_t)((p + 1) & 1)*NLAYER*BH;
        for (int l = 0; l < NLAYER; l++) {
            const float* xin = (l == 0)
                ? ((p == 0) ? hb + ((size_t)3*2 + 0)*BH          // h_{3,T-1} parity (127+3)&1=0
                            : hdprev + (size_t)3*BH)
                : hdcur + (size_t)(l-1)*BH;
            const float* hin = (p == 0)
                ? hb + ((size_t)l*2 + ((127 + l) & 1))*BH        // encoder final hidden of layer l
                : hdprev + (size_t)l*BH;
            dec_partial<<<dg, 256>>>(xin, dWih + (size_t)l*HH, hin, dWhh + (size_t)l*HH, part);
            dec_reduce<<<BH/4/256, 256>>>(part, dbih + l*HIDDEN, dbhh + l*HIDDEN,
                                          hdcur + (size_t)l*BH,
                                          (l == NLAYER-1) ? (dout + (size_t)p*HIDDEN) : nullptr);
        }
    }

    // final FC
    fc_kernel<<<BATCH*PRED/8, 256>>>(dout, fcW, fcb, dec_final);
}